// round 14
// baseline (speedup 1.0000x reference)
#include <cuda_runtime.h>
#include <cstdint>

#define LL   50
#define DD   64
#define EE   128
#define UU   256     // hidden units total
#define UH   128     // hidden units per pass (2 passes)
#define NT   256     // 8 warps; 3 CTAs/SM

#define FFMA2(acc, w, k) asm("fma.rn.f32x2 %0, %1, %2, %0;" : "+l"(acc) : "l"(w), "l"(k))
#define PACK2(dst, f)    asm("mov.b64 %0, {%1, %1};" : "=l"(dst) : "r"(__float_as_uint(f)))
#define UNPK2(lo, hi, s) do { unsigned _ulo, _uhi; \
    asm("mov.b64 {%0, %1}, %2;" : "=r"(_ulo), "=r"(_uhi) : "l"(s)); \
    lo = __uint_as_float(_ulo); hi = __uint_as_float(_uhi); } while (0)

// smem floats: sW2q 128*128 | sq 128 | sAbh 128 | sAq 8*128 | sWout 256 | s_part[4][64]
// + pointer tables spit/spct[56] (8B each) + sactive[56] + scnt[2]
#define SMEM_FLOATS (128*UH + 128 + 128 + 1024 + 256 + 256)
#define SMEM_BYTES  (SMEM_FLOATS*4 + 2*56*8 + 56*4 + 16)

extern "C" __global__ void __launch_bounds__(NT, 3)
din_fused_kernel(const int*   __restrict__ qid_item,
                 const int*   __restrict__ qid_cate,
                 const int*   __restrict__ sid_item,
                 const int*   __restrict__ sid_cate,
                 const int*   __restrict__ mask,    // bool widened to 4B; nonzero == true
                 const float* __restrict__ emb_item,
                 const float* __restrict__ emb_cate,
                 const float* __restrict__ W_hide,
                 const float* __restrict__ b_hide,
                 const float* __restrict__ W_out,
                 const float* __restrict__ b_out,
                 float*       __restrict__ out)
{
    extern __shared__ float smem[];
    float* sW2q   = smem;                    // [128 d][128 u_local] (reused per pass)
    float* sq     = sW2q + 128*UH;           // [128]
    float* sAbh   = sq   + 128;              // [128] (per pass)
    float* sAq    = sAbh + 128;              // [8][128] strip partials
    float* sWout  = sAq  + 8*UH;             // [256]
    float* s_part = sWout + UU;              // [2 pass][64]
    const float** spit = (const float**)(s_part + 256);  // [56] item row ptrs (active)
    const float** spct = spit + 56;                      // [56] cate row ptrs (active)
    int*   sactive= (int*)(spct + 56);       // [56]
    int*   scnt   = sactive + 56;            // [2]

    const int b    = blockIdx.x;
    const int tid  = threadIdx.x;
    const int warp = tid >> 5;
    const int lane = tid & 31;

    // ---------------- Phase 1: q gather + ballot compaction + row ptrs -------
    unsigned bal = 0; bool act = false;
    if (warp < 2) {
        const int l = (warp << 5) + lane;
        act = (l < LL) && (mask[(size_t)b*LL + l] != 0);
        bal = __ballot_sync(0xffffffffu, act);
        if (lane == 0) scnt[warp] = __popc(bal);
    }
    if (tid < EE) {
        const int qi = qid_item[b];
        const int qc = qid_cate[b];
        sq[tid] = (tid < DD) ? emb_item[(size_t)qi*DD + tid]
                             : emb_cate[(size_t)qc*DD + (tid - DD)];
    }
    sWout[tid] = W_out[tid];                  // NT == 256 == UU
    __syncthreads();

    // compaction write (deterministic order via ballot prefix)
    if (warp < 2 && act) {
        const int l   = (warp << 5) + lane;
        const int off = (warp == 1) ? scnt[0] : 0;
        const int pos = off + __popc(bal & ((1u << lane) - 1u));
        sactive[pos] = l;
        spit[pos] = emb_item + (size_t)sid_item[(size_t)b*LL + l]*DD;
        spct[pos] = emb_cate + (size_t)sid_cate[(size_t)b*LL + l]*DD;
    }
    __syncthreads();

    const int nact = scnt[0] + scnt[1];

    // ================= Two passes over u-halves ==============================
    #pragma unroll 1
    for (int h = 0; h < 2; h++) {
        const int gub = h << 7;               // global u base of this half

        // ---- Phase 2: fold W2q = Wk + q*Wp for this half; Aq partials -------
        {
            const int u4 = lane << 2;         // 4 consecutive local u
            const int d0 = warp << 4;         // 16 d-rows per warp strip
            const int gu = gub + u4;
            float4 aq = make_float4(0.f, 0.f, 0.f, 0.f);
            #pragma unroll 4
            for (int i = 0; i < 16; i++) {
                const int d = d0 + i;
                const float qd = sq[d];
                const float4 wk = *(const float4*)(W_hide + (size_t)(128 + d)*UU + gu);
                const float4 wp = *(const float4*)(W_hide + (size_t)(256 + d)*UU + gu);
                const float4 wq = *(const float4*)(W_hide + (size_t)d*UU + gu);
                float4 w2;
                w2.x = fmaf(qd, wp.x, wk.x);
                w2.y = fmaf(qd, wp.y, wk.y);
                w2.z = fmaf(qd, wp.z, wk.z);
                w2.w = fmaf(qd, wp.w, wk.w);
                *(float4*)(sW2q + (d << 7) + u4) = w2;
                aq.x = fmaf(qd, wq.x, aq.x);
                aq.y = fmaf(qd, wq.y, aq.y);
                aq.z = fmaf(qd, wq.z, aq.z);
                aq.w = fmaf(qd, wq.w, aq.w);
            }
            *(float4*)(sAq + warp*UH + u4) = aq;
        }
        __syncthreads();
        if (tid < UH) {
            float a = b_hide[gub + tid];
            #pragma unroll
            for (int s = 0; s < 8; s++) a += sAq[s*UH + tid];
            sAbh[tid] = a;
        }
        __syncthreads();

        // ---- Phase 3: mainloop, 4-l tiles strided over warps; kv via LDG ----
        for (int base = warp << 2; base < nact; base += 32) {
            int nv = nact - base; if (nv > 4) nv = 4;

            const int up = lane << 2;          // 4 local u per lane (2 packed pairs)
            const unsigned long long* ab = (const unsigned long long*)(sAbh + up);
            const unsigned long long i00 = ab[0], i01 = ab[1];
            unsigned long long A[4][2];
            #pragma unroll
            for (int t = 0; t < 4; t++) { A[t][0] = i00; A[t][1] = i01; }

            // two d-halves: [0,64) from item rows, [64,128) from cate rows
            #pragma unroll 1
            for (int half = 0; half < 2; half++) {
                const float** ptab = half ? spct : spit;
                const float* p0 = ptab[base];
                const float* p1 = ptab[(nv > 1) ? base + 1 : base];
                const float* p2 = ptab[(nv > 2) ? base + 2 : base];
                const float* p3 = ptab[(nv > 3) ? base + 3 : base];
                const int dbase = half << 6;

                #pragma unroll 2
                for (int dq = 0; dq < 64; dq += 4) {
                    float4 kv0 = *(const float4*)(p0 + dq);   // uniform LDG (L2 hit)
                    float4 kv1 = *(const float4*)(p1 + dq);
                    float4 kv2 = *(const float4*)(p2 + dq);
                    float4 kv3 = *(const float4*)(p3 + dq);

                    #pragma unroll
                    for (int dd = 0; dd < 4; dd++) {
                        const ulonglong2 wA =
                            *(const ulonglong2*)(sW2q + ((dbase + dq + dd) << 7) + up);
                        unsigned long long kp;
                        PACK2(kp, ((const float*)&kv0)[dd]);
                        FFMA2(A[0][0], wA.x, kp); FFMA2(A[0][1], wA.y, kp);
                        PACK2(kp, ((const float*)&kv1)[dd]);
                        FFMA2(A[1][0], wA.x, kp); FFMA2(A[1][1], wA.y, kp);
                        PACK2(kp, ((const float*)&kv2)[dd]);
                        FFMA2(A[2][0], wA.x, kp); FFMA2(A[2][1], wA.y, kp);
                        PACK2(kp, ((const float*)&kv3)[dd]);
                        FFMA2(A[3][0], wA.x, kp); FFMA2(A[3][1], wA.y, kp);
                    }
                }
            }

            // relu + W_out dot (partial over this half's 4 u's per lane)
            const float w0 = sWout[gub+up+0], w1 = sWout[gub+up+1];
            const float w2_= sWout[gub+up+2], w3 = sWout[gub+up+3];
            float s[4];
            #pragma unroll
            for (int t = 0; t < 4; t++) {
                float lo, hi, acc;
                UNPK2(lo, hi, A[t][0]); acc  = fmaxf(lo,0.f)*w0 + fmaxf(hi,0.f)*w1;
                UNPK2(lo, hi, A[t][1]); acc += fmaxf(lo,0.f)*w2_+ fmaxf(hi,0.f)*w3;
                s[t] = acc;
            }
            #pragma unroll
            for (int t = 0; t < 4; t++) {
                #pragma unroll
                for (int off = 16; off > 0; off >>= 1)
                    s[t] += __shfl_xor_sync(0xffffffffu, s[t], off);
            }
            if (lane == 0) {
                float* dst = s_part + (h << 6);
                #pragma unroll
                for (int t = 0; t < 4; t++)
                    if (t < nv) dst[base + t] = s[t];
            }
        }
        __syncthreads();   // sW2q/sAbh reused next pass; s_part[h] complete
    }

    // ---------------- Phase 4: weighted sum via coalesced LDG + store --------
    if (tid < EE) {
        const float bo = b_out[0];
        float acc = 0.f;
        for (int i = 0; i < nact; i++) {
            const float kv = (tid < DD) ? spit[i][tid] : spct[i][tid - DD];
            acc = fmaf(s_part[i] + s_part[64 + i] + bo, kv, acc);
        }
        out[(size_t)b*EE + tid] = acc;
    }
}

extern "C" void kernel_launch(void* const* d_in, const int* in_sizes, int n_in,
                              void* d_out, int out_size)
{
    const int*   qid_item = (const int*)  d_in[0];
    const int*   qid_cate = (const int*)  d_in[1];
    const int*   sid_item = (const int*)  d_in[2];
    const int*   sid_cate = (const int*)  d_in[3];
    const int*   mask     = (const int*)  d_in[4];
    const float* emb_item = (const float*)d_in[5];
    const float* emb_cate = (const float*)d_in[6];
    const float* W_hide   = (const float*)d_in[7];
    const float* b_hide   = (const float*)d_in[8];
    const float* W_out    = (const float*)d_in[9];
    const float* b_out    = (const float*)d_in[10];
    float*       out      = (float*)      d_out;

    const int B = in_sizes[0];

    cudaFuncSetAttribute(din_fused_kernel,
                         cudaFuncAttributeMaxDynamicSharedMemorySize, SMEM_BYTES);

    din_fused_kernel<<<B, NT, SMEM_BYTES>>>(
        qid_item, qid_cate, sid_item, sid_cate, mask,
        emb_item, emb_cate, W_hide, b_hide, W_out, b_out, out);
}

// round 16
// speedup vs baseline: 1.4889x; 1.4889x over previous
#include <cuda_runtime.h>
#include <cstdint>

#define LL   50
#define DD   64
#define EE   128
#define UU   256
#define NT   256     // 8 warps; 2 CTAs/SM

// ---- smem byte map -------------------------------------------------------
#define OFF_ABIG 0          // A frag big:  [4 mt][8 ks][32 lane][4 u32] = 16384
#define OFF_ASML 16384      // A frag small                               16384
#define OFF_BBIG 32768      // B frag big:  [8 ks][32 lane][34 u32] = 34816
#define OFF_BSML 67584      // B frag small                           34816
#define OFF_PTR  102400
#define SMEM_BYTES 109952

// pack two f32 -> bf16x2 (lo -> low half, hi -> high half)
#define CVT2(r, lo, hi) asm("cvt.rn.bf16x2.f32 %0, %1, %2;" : "=r"(r) : "f"(hi), "f"(lo))

#define MMA_BF16(D, A, B) \
    asm volatile("mma.sync.aligned.m16n8k16.row.col.f32.bf16.bf16.f32 " \
        "{%0,%1,%2,%3},{%4,%5,%6,%7},{%8,%9},{%0,%1,%2,%3};" \
        : "+f"((D)[0]), "+f"((D)[1]), "+f"((D)[2]), "+f"((D)[3]) \
        : "r"((A).x), "r"((A).y), "r"((A).z), "r"((A).w), "r"((B).x), "r"((B).y))

extern "C" __global__ void __launch_bounds__(NT, 2)
din_fused_kernel(const int*   __restrict__ qid_item,
                 const int*   __restrict__ qid_cate,
                 const int*   __restrict__ sid_item,
                 const int*   __restrict__ sid_cate,
                 const int*   __restrict__ mask,    // bool widened to 4B
                 const float* __restrict__ emb_item,
                 const float* __restrict__ emb_cate,
                 const float* __restrict__ W_hide,
                 const float* __restrict__ b_hide,
                 const float* __restrict__ W_out,
                 const float* __restrict__ b_out,
                 float*       __restrict__ out)
{
    extern __shared__ char smem[];
    uint32_t* Abig = (uint32_t*)(smem + OFF_ABIG);
    uint32_t* Asml = (uint32_t*)(smem + OFF_ASML);
    uint32_t* Bbig = (uint32_t*)(smem + OFF_BBIG);
    uint32_t* Bsml = (uint32_t*)(smem + OFF_BSML);
    const float** spit = (const float**)(smem + OFF_PTR);  // [56]
    const float** spct = spit + 56;                        // [56]
    float* sq    = (float*)(spct + 56);                    // [128]
    float* sAq   = sq + 128;                               // [8][128]
    float* sAbh  = sAq + 1024;                             // [128]
    float* s_wm  = sAbh + 128;                             // [4][64]
    float* s_sc  = s_wm + 256;                             // [64]
    int* sactive = (int*)(s_sc + 64);                      // [56]
    int* scnt    = sactive + 56;                           // [2]

    const int b    = blockIdx.x;
    const int tid  = threadIdx.x;
    const int warp = tid >> 5;
    const int lane = tid & 31;

    // ---------------- Phase 1: q gather, compaction, row ptrs ----------------
    unsigned bal = 0; bool act = false;
    if (warp < 2) {
        const int l = (warp << 5) + lane;
        act = (l < LL) && (mask[(size_t)b*LL + l] != 0);
        bal = __ballot_sync(0xffffffffu, act);
        if (lane == 0) scnt[warp] = __popc(bal);
    }
    if (tid < EE) {
        const int qi = qid_item[b];
        const int qc = qid_cate[b];
        sq[tid] = (tid < DD) ? emb_item[(size_t)qi*DD + tid]
                             : emb_cate[(size_t)qc*DD + (tid - DD)];
    }
    s_wm[tid] = 0.f;      // NT == 256 == 4*64
    __syncthreads();

    if (warp < 2 && act) {
        const int l   = (warp << 5) + lane;
        const int off = (warp == 1) ? scnt[0] : 0;
        const int pos = off + __popc(bal & ((1u << lane) - 1u));
        sactive[pos] = l;
        spit[pos] = emb_item + (size_t)sid_item[(size_t)b*LL + l]*DD;
        spct[pos] = emb_cate + (size_t)sid_cate[(size_t)b*LL + l]*DD;
    }
    __syncthreads();

    const int nact   = scnt[0] + scnt[1];
    const int mtiles = (nact + 15) >> 4;      // <= 4

    // ---------------- A-fill: k tile -> bf16-split fragments -----------------
    // slot s = (mt, ks, lane2); regs r=0..3: l = mt*16+g+((r&1)<<3),
    // d = ks*16 + t2 + ((r>>1)<<3); pair (d, d+1).
    for (int s = tid; s < mtiles*256; s += NT) {
        const int lane2 = s & 31;
        const int ks    = (s >> 5) & 7;
        const int mt    = s >> 8;
        const int g     = lane2 >> 2;
        const int t2    = (lane2 & 3) << 1;
        uint4 big, sml;
        uint32_t* bg = (uint32_t*)&big;
        uint32_t* sm = (uint32_t*)&sml;
        #pragma unroll
        for (int r = 0; r < 4; r++) {
            const int l  = mt*16 + g + ((r & 1) << 3);
            const int dd = ks*16 + t2 + ((r >> 1) << 3);
            float2 v = make_float2(0.f, 0.f);
            if (l < nact) {
                const float* p = (ks < 4) ? spit[l] : spct[l];
                v = *(const float2*)(p + (dd - ((ks < 4) ? 0 : 64)));
            }
            uint32_t B_;
            CVT2(B_, v.x, v.y);
            bg[r] = B_;
            const float rx = v.x - __uint_as_float(B_ << 16);
            const float ry = v.y - __uint_as_float(B_ & 0xffff0000u);
            uint32_t S_;
            CVT2(S_, rx, ry);
            sm[r] = S_;
        }
        const int idx = ((mt*8 + ks)*32 + lane2);
        ((uint4*)Abig)[idx] = big;
        ((uint4*)Asml)[idx] = sml;
    }

    // ================= Two passes over u-halves (128 u each) =================
    #pragma unroll 1
    for (int pass = 0; pass < 2; pass++) {
        // ---- Fold B: W2q = Wk + q*Wp, bf16-split fragments; Abh partials ----
        // warp = ks; item i: d = warp*16 + 2i; lane covers u0 = lane*4 .. +3.
        {
            const int u0 = lane << 2;
            const int gu = (pass << 7) + u0;
            float4 abh = make_float4(0.f, 0.f, 0.f, 0.f);
            #pragma unroll
            for (int i = 0; i < 8; i++) {
                const int d  = warp*16 + 2*i;
                const float qd0 = sq[d], qd1 = sq[d+1];
                const float4 wk0 = *(const float4*)(W_hide + (size_t)(128+d)*UU + gu);
                const float4 wk1 = *(const float4*)(W_hide + (size_t)(129+d)*UU + gu);
                const float4 wp0 = *(const float4*)(W_hide + (size_t)(256+d)*UU + gu);
                const float4 wp1 = *(const float4*)(W_hide + (size_t)(257+d)*UU + gu);
                const float4 wq0 = *(const float4*)(W_hide + (size_t)d*UU + gu);
                const float4 wq1 = *(const float4*)(W_hide + (size_t)(d+1)*UU + gu);
                float a[4], c[4];
                a[0]=fmaf(qd0,wp0.x,wk0.x); a[1]=fmaf(qd0,wp0.y,wk0.y);
                a[2]=fmaf(qd0,wp0.z,wk0.z); a[3]=fmaf(qd0,wp0.w,wk0.w);
                c[0]=fmaf(qd1,wp1.x,wk1.x); c[1]=fmaf(qd1,wp1.y,wk1.y);
                c[2]=fmaf(qd1,wp1.z,wk1.z); c[3]=fmaf(qd1,wp1.w,wk1.w);
                abh.x = fmaf(qd0,wq0.x, fmaf(qd1,wq1.x, abh.x));
                abh.y = fmaf(qd0,wq0.y, fmaf(qd1,wq1.y, abh.y));
                abh.z = fmaf(qd0,wq0.z, fmaf(qd1,wq1.z, abh.z));
                abh.w = fmaf(qd0,wq0.w, fmaf(qd1,wq1.w, abh.w));
                const int tig = i & 3;
                const int r   = (i >= 4);
                #pragma unroll
                for (int cc = 0; cc < 4; cc++) {
                    const int u     = u0 + cc;
                    const int nt    = u >> 3;
                    const int lanep = ((u & 7) << 2) + tig;
                    const int boff  = warp*1088 + lanep*34 + nt*2 + r;
                    uint32_t B_;
                    CVT2(B_, a[cc], c[cc]);
                    Bbig[boff] = B_;
                    const float rx = a[cc] - __uint_as_float(B_ << 16);
                    const float ry = c[cc] - __uint_as_float(B_ & 0xffff0000u);
                    uint32_t S_;
                    CVT2(S_, rx, ry);
                    Bsml[boff] = S_;
                }
            }
            *(float4*)(sAq + warp*128 + u0) = abh;
        }
        __syncthreads();
        if (tid < 128) {
            float acc = b_hide[(pass << 7) + tid];
            #pragma unroll
            for (int s = 0; s < 8; s++) acc += sAq[s*128 + tid];
            sAbh[tid] = acc;
        }
        __syncthreads();

        // ---- MMA mainloop: warp = (mtw = w&1) x (nspan = w>>1 -> 4 n8) ------
        {
            const int mtw = warp & 1;
            const int ntb = (warp >> 1) << 2;
            const int g   = lane >> 2;
            const int t2  = (lane & 3) << 1;

            for (int mt = mtw; mt < mtiles; mt += 2) {
                float D[4][4];
                #pragma unroll
                for (int j = 0; j < 4; j++)
                    D[j][0]=D[j][1]=D[j][2]=D[j][3]=0.f;

                #pragma unroll 1
                for (int ks = 0; ks < 8; ks++) {
                    const int aidx = ((mt*8 + ks)*32 + lane);
                    const uint4 Ab = ((const uint4*)Abig)[aidx];
                    const uint4 As = ((const uint4*)Asml)[aidx];
                    #pragma unroll
                    for (int j = 0; j < 4; j++) {
                        const int boff = ks*1088 + lane*34 + (ntb + j)*2;
                        const uint2 Bb = *(const uint2*)(Bbig + boff);
                        const uint2 Bs = *(const uint2*)(Bsml + boff);
                        MMA_BF16(D[j], Ab, Bb);
                        MMA_BF16(D[j], Ab, Bs);
                        MMA_BF16(D[j], As, Bb);
                    }
                }

                // epilogue: + Abh, relu, dot W_out; rows l = mt*16+g, +8
                float sc0 = 0.f, sc1 = 0.f;
                #pragma unroll
                for (int j = 0; j < 4; j++) {
                    const int ul = ((ntb + j) << 3) + t2;
                    const float2 a2 = *(const float2*)(sAbh + ul);
                    const float2 w2 = *(const float2*)(W_out + (pass << 7) + ul);
                    sc0 += fmaxf(D[j][0] + a2.x, 0.f)*w2.x + fmaxf(D[j][1] + a2.y, 0.f)*w2.y;
                    sc1 += fmaxf(D[j][2] + a2.x, 0.f)*w2.x + fmaxf(D[j][3] + a2.y, 0.f)*w2.y;
                }
                sc0 += __shfl_xor_sync(0xffffffffu, sc0, 1);
                sc0 += __shfl_xor_sync(0xffffffffu, sc0, 2);
                sc1 += __shfl_xor_sync(0xffffffffu, sc1, 1);
                sc1 += __shfl_xor_sync(0xffffffffu, sc1, 2);
                if ((lane & 3) == 0) {
                    float* dst = s_wm + ((warp >> 1) << 6);
                    dst[mt*16 + g]     += sc0;
                    dst[mt*16 + g + 8] += sc1;
                }
            }
        }
        __syncthreads();   // B frags reused next pass; s_wm writes visible
    }

    // ---------------- Final: combine scores + weighted sum + store -----------
    if (tid < 64)
        s_sc[tid] = (tid < nact)
            ? (s_wm[tid] + s_wm[64 + tid]) + (s_wm[128 + tid] + s_wm[192 + tid]) + b_out[0]
            : 0.f;
    __syncthreads();

    if (tid < EE) {
        float acc = 0.f;
        for (int i = 0; i < nact; i++) {
            const float kv = (tid < DD) ? spit[i][tid] : spct[i][tid - DD];
            acc = fmaf(s_sc[i], kv, acc);
        }
        out[(size_t)b*EE + tid] = acc;
    }
}

extern "C" void kernel_launch(void* const* d_in, const int* in_sizes, int n_in,
                              void* d_out, int out_size)
{
    const int*   qid_item = (const int*)  d_in[0];
    const int*   qid_cate = (const int*)  d_in[1];
    const int*   sid_item = (const int*)  d_in[2];
    const int*   sid_cate = (const int*)  d_in[3];
    const int*   mask     = (const int*)  d_in[4];
    const float* emb_item = (const float*)d_in[5];
    const float* emb_cate = (const float*)d_in[6];
    const float* W_hide   = (const float*)d_in[7];
    const float* b_hide   = (const float*)d_in[8];
    const float* W_out    = (const float*)d_in[9];
    const float* b_out    = (const float*)d_in[10];
    float*       out      = (float*)      d_out;

    const int B = in_sizes[0];

    cudaFuncSetAttribute(din_fused_kernel,
                         cudaFuncAttributeMaxDynamicSharedMemorySize, SMEM_BYTES);

    din_fused_kernel<<<B, NT, SMEM_BYTES>>>(
        qid_item, qid_cate, sid_item, sid_cate, mask,
        emb_item, emb_cate, W_hide, b_hide, W_out, b_out, out);
}